// round 10
// baseline (speedup 1.0000x reference)
#include <cuda_runtime.h>
#include <cuda_fp16.h>
#include <math.h>
#include <stdint.h>

#define D_MODEL 1024
#define NHEADS  16
#define HD      64
#define SEQ     2048
#define BATCH   2
#define WIN     256

// Scratch (allocation-free: __device__ globals). All fp16.
__device__ __half g_Q[BATCH * NHEADS * SEQ * HD];   // [b][h][l][d]
__device__ __half g_K[BATCH * NHEADS * SEQ * HD];
__device__ __half g_V[BATCH * NHEADS * SEQ * HD];
__device__ __half g_O[BATCH * SEQ * D_MODEL];       // [b][l][h*64+d]
__device__ __half c_x [BATCH * SEQ * D_MODEL];
__device__ __half c_w1[3 * D_MODEL * D_MODEL];
__device__ __half c_w2[D_MODEL * D_MODEL];

__device__ __forceinline__ void mma_f16(float c[4], const unsigned a[4], const unsigned b[2]) {
    asm volatile(
        "mma.sync.aligned.m16n8k16.row.col.f32.f16.f16.f32 "
        "{%0,%1,%2,%3}, {%4,%5,%6,%7}, {%8,%9}, {%0,%1,%2,%3};\n"
        : "+f"(c[0]), "+f"(c[1]), "+f"(c[2]), "+f"(c[3])
        : "r"(a[0]), "r"(a[1]), "r"(a[2]), "r"(a[3]),
          "r"(b[0]), "r"(b[1]));
}

__device__ __forceinline__ void ldsm_x4(unsigned a[4], unsigned saddr) {
    asm volatile("ldmatrix.sync.aligned.m8n8.x4.shared.b16 {%0,%1,%2,%3}, [%4];"
        : "=r"(a[0]), "=r"(a[1]), "=r"(a[2]), "=r"(a[3]) : "r"(saddr));
}

// ---------------------------------------------------------------------------
// fp32 -> fp16 bulk converter
// ---------------------------------------------------------------------------
__global__ void cvt_f16(const float4* __restrict__ in, uint2* __restrict__ out, int n4)
{
    int i = blockIdx.x * blockDim.x + threadIdx.x;
    if (i < n4) {
        float4 v = in[i];
        __half2 h01 = __floats2half2_rn(v.x, v.y);
        __half2 h23 = __floats2half2_rn(v.z, v.w);
        uint2 u;
        u.x = *(unsigned*)&h01;
        u.y = *(unsigned*)&h23;
        out[i] = u;
    }
}

// ---------------------------------------------------------------------------
// FP16 NT GEMM (fp32 accum), BK=64, 3-stage cp.async pipeline + ldmatrix.
// (unchanged from R9)
// ---------------------------------------------------------------------------
#define SSTR 72
#define BK   64
#define STG_HALVES (128 * SSTR)
#define STG_BYTES  (STG_HALVES * 2)
#define NSTG 3

template <int MODE>
__global__ __launch_bounds__(256, 2)
void gemm_f16(const __half* __restrict__ A, const __half* __restrict__ W,
              const float* __restrict__ bias, float* __restrict__ Cout,
              int M, int N, int K)
{
    extern __shared__ __half sh[];
    __half* AsBase = sh;
    __half* BsBase = sh + NSTG * STG_HALVES;

    const __half* Ap = (MODE == 1) ? (const __half*)g_O : A;

    int tid  = threadIdx.x;
    int lane = tid & 31;
    int wid  = tid >> 5;
    int wm = (wid >> 2) * 64;
    int wn = (wid & 3) * 32;
    int bm = blockIdx.y * 128;
    int bn = blockIdx.x * 128;
    int g = lane >> 2;
    int t = lane & 3;
    int lr = lane & 7;

    int a_off = (wm + lr + (((lane >> 3) & 1) ? 8 : 0)) * SSTR + ((lane >> 4) ? 8 : 0);
    int b_off = (wn + lr + ((lane >> 4) ? 8 : 0)) * SSTR + (((lane >> 3) & 1) ? 8 : 0);

    unsigned shA = (unsigned)__cvta_generic_to_shared(AsBase);
    unsigned shB = (unsigned)__cvta_generic_to_shared(BsBase);

    float acc[4][4][4];
#pragma unroll
    for (int mt = 0; mt < 4; mt++)
#pragma unroll
        for (int nt = 0; nt < 4; nt++)
#pragma unroll
            for (int i = 0; i < 4; i++) acc[mt][nt][i] = 0.f;

    auto issue = [&](int s, int k0) {
        __half* dA = AsBase + s * STG_HALVES;
        __half* dB = BsBase + s * STG_HALVES;
#pragma unroll
        for (int r = 0; r < 4; r++) {
            int id  = tid + r * 256;
            int row = id >> 3;
            int c   = id & 7;
            const __half* ga = Ap + (size_t)(bm + row) * K + k0 + c * 8;
            const __half* gb = W  + (size_t)(bn + row) * K + k0 + c * 8;
            unsigned sa = (unsigned)__cvta_generic_to_shared(dA + row * SSTR + c * 8);
            unsigned sb = (unsigned)__cvta_generic_to_shared(dB + row * SSTR + c * 8);
            asm volatile("cp.async.cg.shared.global [%0], [%1], 16;\n" :: "r"(sa), "l"(ga));
            asm volatile("cp.async.cg.shared.global [%0], [%1], 16;\n" :: "r"(sb), "l"(gb));
        }
        asm volatile("cp.async.commit_group;\n");
    };

    const int TILES = K / BK;
    issue(0, 0);
    issue(1, BK);

    int stage = 0, fill = 2;

    for (int t2 = 0; t2 < TILES; t2++) {
        asm volatile("cp.async.wait_group 1;\n" ::: "memory");
        __syncthreads();

        if (t2 + 2 < TILES) issue(fill, (t2 + 2) * BK);

        unsigned stA = shA + stage * STG_BYTES;
        unsigned stB = shB + stage * STG_BYTES;

#pragma unroll
        for (int ks = 0; ks < 4; ks++) {
            int kk = ks * 16;
            unsigned af[4][4], bf[2][4];
#pragma unroll
            for (int mt = 0; mt < 4; mt++)
                ldsm_x4(af[mt], stA + (unsigned)(a_off + mt * 16 * SSTR + kk) * 2);
#pragma unroll
            for (int p = 0; p < 2; p++)
                ldsm_x4(bf[p], stB + (unsigned)(b_off + p * 16 * SSTR + kk) * 2);
#pragma unroll
            for (int mt = 0; mt < 4; mt++)
#pragma unroll
                for (int nt = 0; nt < 4; nt++)
                    mma_f16(acc[mt][nt], af[mt], &bf[nt >> 1][(nt & 1) * 2]);
        }

        fill  = stage;
        stage = (stage == 2) ? 0 : stage + 1;
    }

#pragma unroll
    for (int mt = 0; mt < 4; mt++) {
#pragma unroll
        for (int nt = 0; nt < 4; nt++) {
#pragma unroll
            for (int i = 0; i < 4; i++) {
                int m = bm + wm + mt * 16 + g + ((i >> 1) ? 8 : 0);
                int n = bn + wn + nt * 8 + t * 2 + (i & 1);
                float v = acc[mt][nt][i] + bias[n];
                if (MODE == 0) {
                    int part   = n >> 10;
                    int within = n & 1023;
                    int h = within >> 6;
                    int d = within & 63;
                    int b = m >> 11;
                    int l = m & 2047;
                    size_t dst = ((size_t)(b * NHEADS + h) * SEQ + l) * HD + d;
                    __half* base = (part == 0) ? g_Q : (part == 1) ? g_K : g_V;
                    base[dst] = __float2half_rn(v);
                } else {
                    Cout[(size_t)m * N + n] = v;
                }
            }
        }
    }
}

// ---------------------------------------------------------------------------
// Sliding-window attention, fp16 mma + ldmatrix.
// Q-tile = 128 queries, 256 threads (8 warps x 16 query rows).
// Per CTA: 6 KV chunks (vs 10 per 128 queries at T=64) -> 40% less staging.
// ---------------------------------------------------------------------------
#define AST 72
#define QT  128

__global__ __launch_bounds__(256)
void attn_mma()
{
    extern __shared__ __half smh[];
    __half* Qs = smh;                  // [q][d]  128 x AST
    __half* Ks = smh + QT * AST;       // [j][d]   64 x AST
    __half* Vt = Ks + 64 * AST;        // [d][j]   64 x AST
    __half* Ps = Vt + 64 * AST;        // [q][j]  128 x AST

    int tid  = threadIdx.x;
    int lane = tid & 31;
    int wid  = tid >> 5;               // 0..7
    int g = lane >> 2;
    int t = lane & 3;
    int lr = lane & 7;

    int bh = blockIdx.y;
    int i0 = blockIdx.x * QT;

    const __half* Qg = g_Q + (size_t)bh * SEQ * HD;
    const __half* Kg = g_K + (size_t)bh * SEQ * HD;
    const __half* Vg = g_V + (size_t)bh * SEQ * HD;

    int rbase = wid * 16;
    int a_off = (rbase + lr + (((lane >> 3) & 1) ? 8 : 0)) * AST + ((lane >> 4) ? 8 : 0);
    int b_off = (lr + ((lane >> 4) ? 8 : 0)) * AST + (((lane >> 3) & 1) ? 8 : 0);

    unsigned shQ = (unsigned)__cvta_generic_to_shared(Qs);
    unsigned shK = (unsigned)__cvta_generic_to_shared(Ks);
    unsigned shV = (unsigned)__cvta_generic_to_shared(Vt);
    unsigned shP = (unsigned)__cvta_generic_to_shared(Ps);

    // Load Q tile (128 rows x 64 halves), scale by 0.125 (exact exponent shift)
    {
        int q = tid >> 1, half_sel = tid & 1;
        const __half2 s2 = __floats2half2_rn(0.125f, 0.125f);
#pragma unroll
        for (int v = 0; v < 4; v++) {
            int c8 = half_sel * 32 + v * 8;
            uint2 raw = *(const uint2*)(Qg + (size_t)(i0 + q) * HD + c8);
            __half2 h0 = __hmul2(*(__half2*)&raw.x, s2);
            __half2 h1 = __hmul2(*(__half2*)&raw.y, s2);
            uint2 raw2 = *(const uint2*)(Qg + (size_t)(i0 + q) * HD + c8 + 4);
            __half2 h2 = __hmul2(*(__half2*)&raw2.x, s2);
            __half2 h3 = __hmul2(*(__half2*)&raw2.y, s2);
            __half* dst = Qs + q * AST + c8;
            *(__half2*)(dst)     = h0;
            *(__half2*)(dst + 2) = h1;
            *(__half2*)(dst + 4) = h2;
            *(__half2*)(dst + 6) = h3;
        }
    }

    int iq0 = i0 + rbase + g;
    int iq1 = iq0 + 8;

    float m0 = -1e30f, m1 = -1e30f, l0 = 0.f, l1 = 0.f;
    float oacc[8][4];
#pragma unroll
    for (int nt = 0; nt < 8; nt++)
#pragma unroll
        for (int i = 0; i < 4; i++) oacc[nt][i] = 0.f;

    int kv_lo = i0 - (WIN - 1);
    if (kv_lo < 0) kv_lo = 0;
    int cs0 = (kv_lo / 64) * 64;
    int cs_end = i0 + QT - 64;         // last chunk start (covers queries up to i0+127)

    for (int cs = cs0; cs <= cs_end; cs += 64) {
        __syncthreads();
        // Stage K [j][d] and V transposed [d][j] — 256 threads, 16 halves each
        {
            int j = tid >> 2;          // 0..63
            int c16 = (tid & 3) * 16;  // 0,16,32,48
            uint4 kraw = *(const uint4*)(Kg + (size_t)(cs + j) * HD + c16);
            *(uint4*)(Ks + j * AST + c16) = kraw;
            uint4 kraw2 = *(const uint4*)(Kg + (size_t)(cs + j) * HD + c16 + 8);
            *(uint4*)(Ks + j * AST + c16 + 8) = kraw2;

            uint4 vraw = *(const uint4*)(Vg + (size_t)(cs + j) * HD + c16);
            const __half* vh = (const __half*)&vraw;
#pragma unroll
            for (int e = 0; e < 8; e++)
                Vt[(c16 + e) * AST + j] = vh[e];
            uint4 vraw2 = *(const uint4*)(Vg + (size_t)(cs + j) * HD + c16 + 8);
            const __half* vh2 = (const __half*)&vraw2;
#pragma unroll
            for (int e = 0; e < 8; e++)
                Vt[(c16 + 8 + e) * AST + j] = vh2[e];
        }
        __syncthreads();

        // S = Q*K^T  (warp rows rbase..rbase+15, 64 j columns)
        float sacc[8][4];
#pragma unroll
        for (int nt = 0; nt < 8; nt++)
#pragma unroll
            for (int i = 0; i < 4; i++) sacc[nt][i] = 0.f;

#pragma unroll
        for (int kk = 0; kk < 4; kk++) {
            int c = kk * 16;
            unsigned af[4], bf[4][4];
            ldsm_x4(af, shQ + (unsigned)(a_off + c) * 2);
#pragma unroll
            for (int p = 0; p < 4; p++)
                ldsm_x4(bf[p], shK + (unsigned)(b_off + p * 16 * AST + c) * 2);
#pragma unroll
            for (int nt = 0; nt < 8; nt++)
                mma_f16(sacc[nt], af, &bf[nt >> 1][(nt & 1) * 2]);
        }

        // Mask + online softmax
        float rmax0 = -1e30f, rmax1 = -1e30f;
#pragma unroll
        for (int nt = 0; nt < 8; nt++) {
#pragma unroll
            for (int e = 0; e < 2; e++) {
                int j = cs + nt * 8 + 2 * t + e;
                if (!((j <= iq0) && (j > iq0 - WIN))) sacc[nt][e] = -1e30f;
                if (!((j <= iq1) && (j > iq1 - WIN))) sacc[nt][2 + e] = -1e30f;
                rmax0 = fmaxf(rmax0, sacc[nt][e]);
                rmax1 = fmaxf(rmax1, sacc[nt][2 + e]);
            }
        }
#pragma unroll
        for (int msk = 1; msk < 4; msk <<= 1) {
            rmax0 = fmaxf(rmax0, __shfl_xor_sync(0xffffffffu, rmax0, msk));
            rmax1 = fmaxf(rmax1, __shfl_xor_sync(0xffffffffu, rmax1, msk));
        }

        float mn0 = fmaxf(m0, rmax0);
        float mn1 = fmaxf(m1, rmax1);
        float cor0 = __expf(m0 - mn0);
        float cor1 = __expf(m1 - mn1);
        m0 = mn0; m1 = mn1;

        float rs0 = 0.f, rs1 = 0.f;
#pragma unroll
        for (int nt = 0; nt < 8; nt++) {
            float p0 = __expf(sacc[nt][0] - mn0);
            float p1 = __expf(sacc[nt][1] - mn0);
            float p2 = __expf(sacc[nt][2] - mn1);
            float p3 = __expf(sacc[nt][3] - mn1);
            rs0 += p0 + p1;
            rs1 += p2 + p3;
            int col = nt * 8 + 2 * t;
            *(__half2*)(Ps + (rbase + g) * AST + col)     = __floats2half2_rn(p0, p1);
            *(__half2*)(Ps + (rbase + g + 8) * AST + col) = __floats2half2_rn(p2, p3);
        }
#pragma unroll
        for (int msk = 1; msk < 4; msk <<= 1) {
            rs0 += __shfl_xor_sync(0xffffffffu, rs0, msk);
            rs1 += __shfl_xor_sync(0xffffffffu, rs1, msk);
        }
        l0 = l0 * cor0 + rs0;
        l1 = l1 * cor1 + rs1;
#pragma unroll
        for (int nt = 0; nt < 8; nt++) {
            oacc[nt][0] *= cor0; oacc[nt][1] *= cor0;
            oacc[nt][2] *= cor1; oacc[nt][3] *= cor1;
        }
        __syncwarp();

        // O += P * V
#pragma unroll
        for (int kk = 0; kk < 4; kk++) {
            int c = kk * 16;
            unsigned af[4], bf[4][4];
            ldsm_x4(af, shP + (unsigned)(a_off + c) * 2);
#pragma unroll
            for (int p = 0; p < 4; p++)
                ldsm_x4(bf[p], shV + (unsigned)(b_off + p * 16 * AST + c) * 2);
#pragma unroll
            for (int nt = 0; nt < 8; nt++)
                mma_f16(oacc[nt], af, &bf[nt >> 1][(nt & 1) * 2]);
        }
    }

    // Normalize + write fp16 O
    float inv0 = 1.f / l0;
    float inv1 = 1.f / l1;
    int b = bh / NHEADS;
    int h = bh % NHEADS;
    __half* O0 = g_O + (size_t)(b * SEQ + iq0) * D_MODEL + h * HD;
    __half* O1 = g_O + (size_t)(b * SEQ + iq1) * D_MODEL + h * HD;
#pragma unroll
    for (int nt = 0; nt < 8; nt++) {
        int d = nt * 8 + 2 * t;
        *(__half2*)(O0 + d) = __floats2half2_rn(oacc[nt][0] * inv0, oacc[nt][1] * inv0);
        *(__half2*)(O1 + d) = __floats2half2_rn(oacc[nt][2] * inv1, oacc[nt][3] * inv1);
    }
}

// ---------------------------------------------------------------------------
extern "C" void kernel_launch(void* const* d_in, const int* in_sizes, int n_in,
                              void* d_out, int out_size)
{
    const float* x  = (const float*)d_in[0];
    const float* w1 = (const float*)d_in[1];
    const float* b1 = (const float*)d_in[2];
    const float* w2 = (const float*)d_in[3];
    const float* b2 = (const float*)d_in[4];
    float* out = (float*)d_out;

    const int M = BATCH * SEQ;

    __half *cx, *cw1, *cw2;
    cudaGetSymbolAddress((void**)&cx,  c_x);
    cudaGetSymbolAddress((void**)&cw1, c_w1);
    cudaGetSymbolAddress((void**)&cw2, c_w2);

    // 0) fp32 -> fp16 conversions
    {
        int n4x = M * D_MODEL / 4;
        cvt_f16<<<(n4x + 255) / 256, 256>>>((const float4*)x, (uint2*)cx, n4x);
        int n4w1 = 3 * D_MODEL * D_MODEL / 4;
        cvt_f16<<<(n4w1 + 255) / 256, 256>>>((const float4*)w1, (uint2*)cw1, n4w1);
        int n4w2 = D_MODEL * D_MODEL / 4;
        cvt_f16<<<(n4w2 + 255) / 256, 256>>>((const float4*)w2, (uint2*)cw2, n4w2);
    }

    const int gemm_smem = 2 * NSTG * STG_BYTES;   // 110592 B

    // 1) QKV projection (fp16 mma, BK=64 pipeline)
    {
        cudaFuncSetAttribute(gemm_f16<0>,
                             cudaFuncAttributeMaxDynamicSharedMemorySize, gemm_smem);
        dim3 grid(3 * D_MODEL / 128, M / 128);
        gemm_f16<0><<<grid, 256, gemm_smem>>>(cx, cw1, b1, nullptr, M, 3 * D_MODEL, D_MODEL);
    }

    // 2) Sliding-window attention (fp16 mma, Q-tile 128)
    {
        int smem = (QT + 64 + 64 + QT) * AST * sizeof(__half);  // 55296 B
        cudaFuncSetAttribute(attn_mma,
                             cudaFuncAttributeMaxDynamicSharedMemorySize, smem);
        dim3 grid(SEQ / QT, BATCH * NHEADS);   // (16, 32)
        attn_mma<<<grid, 256, smem>>>();
    }

    // 3) Output projection (fp16 mma)
    {
        cudaFuncSetAttribute(gemm_f16<1>,
                             cudaFuncAttributeMaxDynamicSharedMemorySize, gemm_smem);
        dim3 grid(D_MODEL / 128, M / 128);
        gemm_f16<1><<<grid, 256, gemm_smem>>>(nullptr, cw2, b2, out, M, D_MODEL, D_MODEL);
    }
}